// round 14
// baseline (speedup 1.0000x reference)
#include <cuda_runtime.h>
#include <cuda_bf16.h>

// Jagged (sorted batch_indexes) -> padded dense, single fused kernel.
//
// Inputs (metadata order):
//   d_in[0] keypoints0    float32 (N,2)
//   d_in[1] keypoints1    float32 (N,2)
//   d_in[2] confidence    float32 (N,)
//   d_in[3] batch_indexes int32 (N,)   -- sorted, contiguous runs
//   d_in[4] num_batches   (scalar)
//   d_in[5] max_points    (scalar)
// Output: concat of source_points (B,L,2), target_points (B,L,2), scores (B,L)
//         => out_size = 5*B*L float32.
//
// Metadata (run start offsets) is found by per-block binary search over the
// sorted batch_indexes: each block spans <= 2 batches when L >= 2*blockDim,
// so 3 lower_bound values in shared memory cover every thread. The search
// latency hides behind the DRAM-bound gather (issue was only ~17% busy).
// Everything is recomputed every launch -> graph-replay deterministic.
// lower_bound semantics reproduce the reference's mode="drop" for any
// negative / out-of-range batch index.

__device__ __forceinline__ int lower_bound_dev(const int* __restrict__ bi,
                                               int n, int key) {
    int lo = 0, hi = n;                 // first index with bi[i] >= key
    while (lo < hi) {
        int mid = (int)(((unsigned)lo + (unsigned)hi) >> 1);
        if (bi[mid] < key) lo = mid + 1;
        else               hi = mid;
    }
    return lo;
}

// Fused: one thread per PAIR of (b,p) output slots; exact grid (no stride).
__global__ void fused_gather_kernel(const float2* __restrict__ kp0,
                                    const float2* __restrict__ kp1,
                                    const float*  __restrict__ conf,
                                    const int*    __restrict__ bi,
                                    float4* __restrict__ out_src,
                                    float4* __restrict__ out_tgt,
                                    float2* __restrict__ out_sc,
                                    const int* __restrict__ max_points_p,
                                    int n, int npairs, int total) {
    __shared__ int s_start[3];

    int L = max_points_p[0];            // little-endian low word ok for i32/i64
    int k = blockIdx.x * blockDim.x + threadIdx.x;   // pair index
    int k0 = blockIdx.x * blockDim.x;                // block's first pair

    // Block-level metadata: batches touched by slots [2*k0, last_slot]
    int first_slot = 2 * k0;
    int last_slot  = 2 * k0 + 2 * blockDim.x - 1;
    if (last_slot > total - 1) last_slot = total - 1;
    int b_first = first_slot / L;
    int b_last  = last_slot  / L;
    int nent = b_last - b_first + 2;    // need g_start[b_first .. b_last+1]

    bool fast = (nent <= 3);
    if (fast) {
        if (threadIdx.x < nent)
            s_start[threadIdx.x] = lower_bound_dev(bi, n, b_first + threadIdx.x);
        __syncthreads();
    }

    if (k >= npairs) return;

    int idx = k * 2;
    int b0 = idx / L;
    int p0 = idx - b0 * L;
    int b1 = (idx + 1) / L;
    int p1 = (idx + 1) - b1 * L;

    int st0, en0, st1, en1;
    if (fast) {
        st0 = s_start[b0 - b_first];
        en0 = s_start[b0 - b_first + 1];
        st1 = s_start[b1 - b_first];
        en1 = s_start[b1 - b_first + 1];
    } else {
        // generic slow path (L < 2*blockDim): per-thread searches
        st0 = lower_bound_dev(bi, n, b0);
        en0 = lower_bound_dev(bi, n, b0 + 1);
        if (b1 == b0) { st1 = st0; en1 = en0; }
        else {
            st1 = en0;
            en1 = lower_bound_dev(bi, n, b1 + 1);
        }
    }

    float4 s = make_float4(0.f, 0.f, 0.f, 0.f);
    float4 t = make_float4(0.f, 0.f, 0.f, 0.f);
    float2 c = make_float2(0.f, 0.f);

    if (p0 < en0 - st0) {
        int j = st0 + p0;
        float2 a = kp0[j], d = kp1[j];
        s.x = a.x; s.y = a.y;
        t.x = d.x; t.y = d.y;
        c.x = conf[j];
    }
    if (p1 < en1 - st1) {
        int j = st1 + p1;
        float2 a = kp0[j], d = kp1[j];
        s.z = a.x; s.w = a.y;
        t.z = d.x; t.w = d.y;
        c.y = conf[j];
    }

    out_src[k] = s;
    out_tgt[k] = t;
    out_sc[k]  = c;
}

// Scalar tail for odd total (not hit for this dataset; kept for correctness).
__global__ void gather_tail_kernel(const float2* __restrict__ kp0,
                                   const float2* __restrict__ kp1,
                                   const float*  __restrict__ conf,
                                   const int*    __restrict__ bi,
                                   float2* __restrict__ out_src,
                                   float2* __restrict__ out_tgt,
                                   float*  __restrict__ out_sc,
                                   const int* __restrict__ max_points_p,
                                   int n, int begin, int total) {
    int idx = begin + blockIdx.x * blockDim.x + threadIdx.x;
    if (idx >= total) return;
    int L = max_points_p[0];
    int b = idx / L;
    int p = idx - b * L;
    int st = lower_bound_dev(bi, n, b);
    int en = lower_bound_dev(bi, n, b + 1);
    float2 s = make_float2(0.f, 0.f), t = make_float2(0.f, 0.f);
    float  c = 0.f;
    if (p < en - st) {
        int j = st + p;
        s = kp0[j]; t = kp1[j]; c = conf[j];
    }
    out_src[idx] = s; out_tgt[idx] = t; out_sc[idx] = c;
}

extern "C" void kernel_launch(void* const* d_in, const int* in_sizes, int n_in,
                              void* d_out, int out_size) {
    const float2* kp0  = (const float2*)d_in[0];
    const float2* kp1  = (const float2*)d_in[1];
    const float*  conf = (const float*)d_in[2];
    const int*    bi   = (const int*)d_in[3];
    const int*    maxp = (const int*)d_in[5];

    int n = in_sizes[2];               // N
    int total = out_size / 5;          // B * L

    float* out = (float*)d_out;
    float2* out_src = (float2*)out;                      // B*L float2
    float2* out_tgt = (float2*)(out + 2LL * total);
    float*  out_sc  = out + 4LL * total;

    int npairs = total / 2;
    if (npairs > 0) {
        const int threads = 256;
        int blocks = (npairs + threads - 1) / threads;   // exact grid
        fused_gather_kernel<<<blocks, threads>>>(kp0, kp1, conf, bi,
                                                 (float4*)out_src,
                                                 (float4*)out_tgt,
                                                 (float2*)out_sc,
                                                 maxp, n, npairs, total);
    }
    int done = npairs * 2;
    if (done < total) {
        int rem = total - done;
        gather_tail_kernel<<<(rem + 255) / 256, 256>>>(kp0, kp1, conf, bi,
                                                       out_src, out_tgt, out_sc,
                                                       maxp, n, done, total);
    }
}